// round 16
// baseline (speedup 1.0000x reference)
#include <cuda_runtime.h>

#define EPSF 1e-5f
constexpr int NCURVE = 2097152;   // B*G*C
constexpr int CSEG   = 128;       // curves per group
constexpr int NGRP   = 16384;     // B*G groups
constexpr int BPIC   = 256;       // pictures
constexpr int GPG    = 64;        // groups per picture

typedef unsigned long long u64;

// ---- scratch (__device__ globals; no allocation allowed) ----
__device__ float g_gsum[NGRP * 12];     // per-group sum of h12 (pre-BN)
__device__ float g_accum[96];           // [0:12) sum h, [12:24) sum h^2,
                                        // [24:60) sum v36, [60:96) sum v36^2
__device__ float g_sumpicT[36 * BPIC];  // TRANSPOSED [36][256] pooled features

// packed weights: [0:384) w1 pairs, [384:528) w2 pairs, [528:540) b1, [540:546) b2
constexpr int WPN = 546;
__device__   u64 g_wp[WPN];            // staging (written by k_pack)
__constant__ u64 c_wp[WPN];            // const-port copy used by k_curves

// ---- packed f32x2 helpers ----
__device__ __forceinline__ u64 pk2(float lo, float hi) {
    u64 r; asm("mov.b64 %0, {%1,%2};" : "=l"(r) : "f"(lo), "f"(hi)); return r;
}
__device__ __forceinline__ void unpk2(u64 v, float& lo, float& hi) {
    asm("mov.b64 {%0,%1}, %2;" : "=f"(lo), "=f"(hi) : "l"(v));
}
__device__ __forceinline__ u64 dup2(float a) {
    u64 r; asm("mov.b64 %0, {%1,%1};" : "=l"(r) : "f"(a)); return r;
}
__device__ __forceinline__ void fma2(u64& d, u64 a, u64 b) {
    asm("fma.rn.f32x2 %0, %1, %2, %0;" : "+l"(d) : "l"(a), "l"(b));
}
__device__ __forceinline__ u64 fma2n(u64 a, u64 b, u64 c) {
    u64 d; asm("fma.rn.f32x2 %0, %1, %2, %3;" : "=l"(d) : "l"(a), "l"(b), "l"(c)); return d;
}
__device__ __forceinline__ u64 mul2(u64 a, u64 b) {
    u64 d; asm("mul.rn.f32x2 %0, %1, %2;" : "=l"(d) : "l"(a), "l"(b)); return d;
}
__device__ __forceinline__ u64 add2(u64 a, u64 b) {
    u64 d; asm("add.rn.f32x2 %0, %1, %2;" : "=l"(d) : "l"(a), "l"(b)); return d;
}
// packed leaky: leaky(v) = 0.505*v + 0.495*|v|
__device__ __forceinline__ u64 lk2(u64 v, u64 c505, u64 c495) {
    u64 a = v & 0x7fffffff7fffffffull;
    return fma2n(a, c495, mul2(v, c505));
}
__device__ __forceinline__ float leaky1(float v) {
    return fmaxf(v, 0.0f) + 0.01f * fminf(v, 0.0f);
}
// fire-and-forget L2 prefetch (no semantic effect; graph-safe)
__device__ __forceinline__ void pfL2(const void* p) {
    asm volatile("prefetch.global.L2 [%0];" :: "l"(p));
}

// ============================================================================
// Kernel 0: pack channel-pair weights into g_wp + zero g_accum.
// ============================================================================
__global__ __launch_bounds__(192) void k_pack(
    const float* __restrict__ w1, const float* __restrict__ b1,
    const float* __restrict__ w2, const float* __restrict__ b2)
{
    int i = blockIdx.x * 192 + threadIdx.x;
    if (i < 96) g_accum[i] = 0.0f;

    if (i < 384) {                       // w1 pairs: [jj][k], k in 0..31
        int jj = i >> 5, k = i & 31;
        g_wp[i] = pk2(w1[(2 * jj) * 32 + k], w1[(2 * jj + 1) * 32 + k]);
    } else if (i < 528) {                // w2 pairs: [jj][k], k in 0..23
        int t = i - 384, jj = t / 24, k = t % 24;
        g_wp[i] = pk2(w2[(2 * jj) * 24 + k], w2[(2 * jj + 1) * 24 + k]);
    } else if (i < 540) {                // b1 pairs
        int t = i - 528;
        g_wp[i] = pk2(b1[2 * t], b1[2 * t + 1]);
    } else if (i < WPN) {                // b2 pairs
        int t = i - 540;
        g_wp[i] = pk2(b2[2 * t], b2[2 * t + 1]);
    }
}

// ============================================================================
// Kernel 1: per-curve MLP 32->24->12 (leaky), per-group sum, global sum/sumsq.
// OCCUPANCY VARIANT: 256 threads/block = 8 warps; 2 warps per group; each
// lane owns 2 curves (halved registers -> 2 blocks/SM = 16 warps/SM,
// vs 12 before) to hide x-load latency. Channel-pair f32x2 packing unchanged.
// ============================================================================
__global__ __launch_bounds__(256, 2) void k_curves(const float* __restrict__ x)
{
    __shared__ float sred[8][24];

    const int tid  = threadIdx.x;
    const int lane = tid & 31, warp = tid >> 5;
    const int grp  = warp >> 1;          // group within block (0..3)
    const int half = warp & 1;           // which 64-curve half of the group
    const int g    = blockIdx.x * 4 + grp;

    // lane's 2 curves: rows (lane + 64*half) and (lane + 32 + 64*half)
    const float4* r0 = (const float4*)x +
        ((size_t)g * CSEG + (size_t)half * 64 + lane) * 8;
    // second curve: +32 rows = +256 float4

    // ---- layer 1: H[c][jj] = packed channels (2jj, 2jj+1) of curve c ----
    u64 H[2][12];
#pragma unroll
    for (int jj = 0; jj < 12; ++jj) {
        u64 b = c_wp[528 + jj];
        H[0][jj] = b; H[1][jj] = b;
    }

#pragma unroll 2
    for (int q = 0; q < 8; ++q) {
        float4 xv0 = r0[q], xv1 = r0[q + 256];
        u64 d0x = dup2(xv0.x), d0y = dup2(xv0.y), d0z = dup2(xv0.z), d0w = dup2(xv0.w);
        u64 d1x = dup2(xv1.x), d1y = dup2(xv1.y), d1z = dup2(xv1.z), d1w = dup2(xv1.w);
#pragma unroll
        for (int jj = 0; jj < 12; ++jj) {
            u64 wa = c_wp[jj * 32 + 4 * q + 0];   // k = 4q
            u64 wb = c_wp[jj * 32 + 4 * q + 1];   // k = 4q+1
            u64 wc = c_wp[jj * 32 + 4 * q + 2];   // k = 4q+2
            u64 wd = c_wp[jj * 32 + 4 * q + 3];   // k = 4q+3
            fma2(H[0][jj], d0x, wa); fma2(H[1][jj], d1x, wa);
            fma2(H[0][jj], d0y, wb); fma2(H[1][jj], d1y, wb);
            fma2(H[0][jj], d0z, wc); fma2(H[1][jj], d1z, wc);
            fma2(H[0][jj], d0w, wd); fma2(H[1][jj], d1w, wd);
        }
    }

    const u64 C505 = dup2(0.505f), C495 = dup2(0.495f);
#pragma unroll
    for (int c = 0; c < 2; ++c)
#pragma unroll
        for (int jj = 0; jj < 12; ++jj) H[c][jj] = lk2(H[c][jj], C505, C495);

    // ---- layer 2: C[c][jj] = packed output channels (2jj, 2jj+1) ----
    u64 C[2][6];
#pragma unroll
    for (int jj = 0; jj < 6; ++jj) {
        u64 b = c_wp[540 + jj];
        C[0][jj] = b; C[1][jj] = b;
    }

#pragma unroll
    for (int kk = 0; kk < 12; ++kk) {                 // input channels 2kk, 2kk+1
        float lo0, hi0, lo1, hi1;
        unpk2(H[0][kk], lo0, hi0);
        unpk2(H[1][kk], lo1, hi1);
        u64 dlo0 = dup2(lo0), dhi0 = dup2(hi0);
        u64 dlo1 = dup2(lo1), dhi1 = dup2(hi1);
#pragma unroll
        for (int jj = 0; jj < 6; ++jj) {
            u64 wlo = c_wp[384 + jj * 24 + 2 * kk];       // input 2kk
            u64 whi = c_wp[384 + jj * 24 + 2 * kk + 1];   // input 2kk+1
            fma2(C[0][jj], dlo0, wlo); fma2(C[0][jj], dhi0, whi);
            fma2(C[1][jj], dlo1, wlo); fma2(C[1][jj], dhi1, whi);
        }
    }

    // leaky + per-thread packed sum / sumsq over the 2 curves
    u64 S[6], Q[6];
#pragma unroll
    for (int jj = 0; jj < 6; ++jj) {
        u64 c0 = lk2(C[0][jj], C505, C495);
        u64 c1 = lk2(C[1][jj], C505, C495);
        S[jj] = add2(c0, c1);
        Q[jj] = fma2n(c1, c1, mul2(c0, c0));
    }

    // warp reduction: each warp covers 64 curves of its group
#pragma unroll
    for (int jj = 0; jj < 6; ++jj) {
#pragma unroll
        for (int off = 16; off > 0; off >>= 1) {
            S[jj] = add2(S[jj], (u64)__shfl_xor_sync(0xffffffffu, (unsigned long long)S[jj], off));
            Q[jj] = add2(Q[jj], (u64)__shfl_xor_sync(0xffffffffu, (unsigned long long)Q[jj], off));
        }
    }
    if (lane == 0) {
#pragma unroll
        for (int jj = 0; jj < 6; ++jj) {
            float slo, shi, qlo, qhi;
            unpk2(S[jj], slo, shi);
            unpk2(Q[jj], qlo, qhi);
            sred[warp][2 * jj]      = slo;
            sred[warp][2 * jj + 1]  = shi;
            sred[warp][12 + 2 * jj]     = qlo;
            sred[warp][12 + 2 * jj + 1] = qhi;
        }
    }
    __syncthreads();

    // combine the 2 warps of each group; write g_gsum; stash combined in sred[2*grp]
    if (tid < 96) {
        int gq = tid / 24, ch = tid % 24;
        float v = sred[2 * gq][ch] + sred[2 * gq + 1][ch];
        if (ch < 12) g_gsum[(blockIdx.x * 4 + gq) * 12 + ch] = v;
        sred[2 * gq][ch] = v;
    }
    __syncthreads();
    if (tid < 24)
        atomicAdd(&g_accum[tid],
                  sred[0][tid] + sred[2][tid] + sred[4][tid] + sred[6][tid]);
}

// ============================================================================
// Kernel 2: per-picture — deferred BN12 on group means, distance MLP,
// 3-level pooling -> g_sumpicT[36][256]; atomic global sum/sumsq for BN36.
// Block 0 L2-prefetches k_head's weights.
// ============================================================================
__global__ __launch_bounds__(64) void k_groups(
    const float* __restrict__ dist,
    const float* __restrict__ gamma12, const float* __restrict__ beta12,
    const float* __restrict__ wd, const float* __restrict__ bd,
    const float* __restrict__ gamma36, const float* __restrict__ beta36,
    const float* __restrict__ wp1, const float* __restrict__ bp1,
    const float* __restrict__ wp2, const float* __restrict__ bp2,
    const float* __restrict__ wp3, const float* __restrict__ bp3)
{
    __shared__ float sc[12], sh[12], wds[60], bds[12];
    __shared__ float red[2][36];
    const int tid = threadIdx.x, b = blockIdx.x;

    // ---- L2 warm-up for k_head (fire-and-forget) ----
    if (b == 0) {
        if (tid < 21) pfL2(wp1 + tid * 32);
        else if (tid < 26) pfL2(wp2 + (tid - 21) * 32);
        else if (tid == 26) { pfL2(wp3); pfL2(bp1); }
        else if (tid == 27) { pfL2(bp2); pfL2(bp3); }
        else if (tid == 28) { pfL2(gamma36); pfL2(beta36); }
        else if (tid == 29) { pfL2(gamma36 + 32); pfL2(beta36 + 32); }
    }

    if (tid < 12) {
        const float n = (float)NCURVE;
        float mu  = g_accum[tid] / n;
        float var = g_accum[12 + tid] / n - mu * mu;
        float ss  = gamma12[tid] * rsqrtf(var + EPSF);
        sc[tid] = ss;
        sh[tid] = beta12[tid] - mu * ss;
    }
    if (tid < 60) wds[tid] = wd[tid];
    if (tid < 12) bds[tid] = bd[tid];
    __syncthreads();

    const int bg = b * GPG + tid;
    const float4* gs4 = (const float4*)(g_gsum + bg * 12);
    float4 h0 = gs4[0], h1 = gs4[1], h2 = gs4[2];
    float h[12] = {h0.x, h0.y, h0.z, h0.w, h1.x, h1.y, h1.z, h1.w,
                   h2.x, h2.y, h2.z, h2.w};
#pragma unroll
    for (int j = 0; j < 12; ++j)
        h[j] = fmaf(h[j] * (1.0f / CSEG), sc[j], sh[j]);

    float d5[5];
#pragma unroll
    for (int k = 0; k < 5; ++k) d5[k] = dist[bg * 10 + k];

    float v[36];
#pragma unroll
    for (int j = 0; j < 12; ++j) {
        float t = bds[j];
#pragma unroll
        for (int k = 0; k < 5; ++k) t = fmaf(wds[j * 5 + k], d5[k], t);
        float cor = leaky1(t);
        float g2 = cor * h[j];
        float g3 = cor * g2;
        v[j] = h[j]; v[12 + j] = g2; v[24 + j] = g3;
    }
#pragma unroll
    for (int j = 0; j < 36; ++j) {
#pragma unroll
        for (int off = 16; off > 0; off >>= 1)
            v[j] += __shfl_xor_sync(0xffffffffu, v[j], off);
    }
    const int warp = tid >> 5;
    if ((tid & 31) == 0) {
#pragma unroll
        for (int j = 0; j < 36; ++j) red[warp][j] = v[j];
    }
    __syncthreads();
    if (tid < 36) {
        float val = (red[0][tid] + red[1][tid]) * (1.0f / GPG);
        g_sumpicT[tid * BPIC + b] = val;      // transposed store
        atomicAdd(&g_accum[24 + tid], val);
        atomicAdd(&g_accum[60 + tid], val * val);
    }
}

// ============================================================================
// Kernel 3: BN36 + head MLP 36->18->8 -> softmax. 8 blocks x 32 pictures.
// ============================================================================
__global__ __launch_bounds__(256) void k_head(
    const float* __restrict__ gamma36, const float* __restrict__ beta36,
    const float* __restrict__ wp1, const float* __restrict__ bp1,
    const float* __restrict__ wp2, const float* __restrict__ bp2,
    const float* __restrict__ wp3, const float* __restrict__ bp3,
    float* __restrict__ out)
{
    __shared__ float w1s[648], b1s[18], w2s[144], b2s[8], w3s[16], b3s[2];
    __shared__ float sc[36], sh[36];
    const int tid = threadIdx.x;

    for (int i = tid; i < 648; i += 256) w1s[i] = wp1[i];
    if (tid < 18)  b1s[tid] = bp1[tid];
    if (tid < 144) w2s[tid] = wp2[tid];
    if (tid < 8)   b2s[tid] = bp2[tid];
    if (tid < 16)  w3s[tid] = wp3[tid];
    if (tid < 2)   b3s[tid] = bp3[tid];

    if (tid < 36) {
        float mu  = g_accum[24 + tid] * (1.0f / 256.0f);
        float var = g_accum[60 + tid] * (1.0f / 256.0f) - mu * mu;
        float ss  = gamma36[tid] * rsqrtf(var + EPSF);
        sc[tid] = ss;
        sh[tid] = beta36[tid] - mu * ss;
    }
    __syncthreads();

    if (tid >= 32) return;                   // 32 pictures per block
    const int p = blockIdx.x * 32 + tid;

    float sN[36];
#pragma unroll
    for (int j = 0; j < 36; ++j)
        sN[j] = fmaf(g_sumpicT[j * BPIC + p], sc[j], sh[j]);

    float p1[18];
#pragma unroll
    for (int j = 0; j < 18; ++j) {
        float t = b1s[j];
#pragma unroll
        for (int k = 0; k < 36; ++k) t = fmaf(w1s[j * 36 + k], sN[k], t);
        p1[j] = leaky1(t);
    }
    float p2[8];
#pragma unroll
    for (int j = 0; j < 8; ++j) {
        float t = b2s[j];
#pragma unroll
        for (int k = 0; k < 18; ++k) t = fmaf(w2s[j * 18 + k], p1[k], t);
        p2[j] = leaky1(t);
    }
    float l0 = b3s[0], l1 = b3s[1];
#pragma unroll
    for (int k = 0; k < 8; ++k) {
        l0 = fmaf(w3s[k],     p2[k], l0);
        l1 = fmaf(w3s[8 + k], p2[k], l1);
    }
    float m  = fmaxf(l0, l1);
    float e0 = expf(l0 - m), e1 = expf(l1 - m);
    float inv = 1.0f / (e0 + e1);

#pragma unroll
    for (int j = 0; j < 8; ++j) out[p * 8 + j] = p2[j];   // p2: [256,8]
    out[BPIC * 8 + p * 2 + 0] = e0 * inv;                 // p3: [256,2]
    out[BPIC * 8 + p * 2 + 1] = e1 * inv;
}

// ============================================================================
extern "C" void kernel_launch(void* const* d_in, const int* in_sizes, int n_in,
                              void* d_out, int out_size)
{
    const float* x       = (const float*)d_in[0];
    const float* dist    = (const float*)d_in[1];
    // d_in[2] = segment_ids: structurally arange/128, unused
    const float* w1      = (const float*)d_in[3];
    const float* b1      = (const float*)d_in[4];
    const float* w2      = (const float*)d_in[5];
    const float* b2      = (const float*)d_in[6];
    const float* gamma12 = (const float*)d_in[7];
    const float* beta12  = (const float*)d_in[8];
    const float* wd      = (const float*)d_in[9];
    const float* bd      = (const float*)d_in[10];
    const float* gamma36 = (const float*)d_in[11];
    const float* beta36  = (const float*)d_in[12];
    const float* wp1     = (const float*)d_in[13];
    const float* bp1     = (const float*)d_in[14];
    const float* wp2     = (const float*)d_in[15];
    const float* bp2     = (const float*)d_in[16];
    const float* wp3     = (const float*)d_in[17];
    const float* bp3     = (const float*)d_in[18];

    // pack weights + zero g_accum, then stage into __constant__ via D2D copy
    k_pack<<<3, 192>>>(w1, b1, w2, b2);
    void* wpp = nullptr;
    cudaGetSymbolAddress(&wpp, g_wp);
    cudaMemcpyToSymbolAsync(c_wp, wpp, WPN * sizeof(u64), 0,
                            cudaMemcpyDeviceToDevice);

    k_curves<<<NGRP / 4, 256>>>(x);
    k_groups<<<BPIC, 64>>>(dist, gamma12, beta12, wd, bd,
                           gamma36, beta36, wp1, bp1, wp2, bp2, wp3, bp3);
    k_head<<<8, 256>>>(gamma36, beta36, wp1, bp1, wp2, bp2, wp3, bp3,
                       (float*)d_out);
}

// round 17
// speedup vs baseline: 1.0582x; 1.0582x over previous
#include <cuda_runtime.h>

#define EPSF 1e-5f
constexpr int NCURVE = 2097152;   // B*G*C
constexpr int CSEG   = 128;       // curves per group
constexpr int NGRP   = 16384;     // B*G groups
constexpr int BPIC   = 256;       // pictures
constexpr int GPG    = 64;        // groups per picture

typedef unsigned long long u64;

// ---- scratch (__device__ globals; no allocation allowed) ----
__device__ float g_gsum[NGRP * 12];     // per-group sum of h12 (pre-BN)
__device__ float g_accum[96];           // [0:12) sum h, [12:24) sum h^2,
                                        // [24:60) sum v36, [60:96) sum v36^2
__device__ float g_sumpicT[36 * BPIC];  // TRANSPOSED [36][256] pooled features

// packed weights: [0:384) w1 pairs, [384:528) w2 pairs, [528:540) b1, [540:546) b2
constexpr int WPN = 546;
__device__   u64 g_wp[WPN];            // staging (written by k_pack)
__constant__ u64 c_wp[WPN];            // const-port copy used by k_curves

// ---- packed f32x2 helpers ----
__device__ __forceinline__ u64 pk2(float lo, float hi) {
    u64 r; asm("mov.b64 %0, {%1,%2};" : "=l"(r) : "f"(lo), "f"(hi)); return r;
}
__device__ __forceinline__ void unpk2(u64 v, float& lo, float& hi) {
    asm("mov.b64 {%0,%1}, %2;" : "=f"(lo), "=f"(hi) : "l"(v));
}
__device__ __forceinline__ u64 dup2(float a) {
    u64 r; asm("mov.b64 %0, {%1,%1};" : "=l"(r) : "f"(a)); return r;
}
__device__ __forceinline__ void fma2(u64& d, u64 a, u64 b) {
    asm("fma.rn.f32x2 %0, %1, %2, %0;" : "+l"(d) : "l"(a), "l"(b));
}
__device__ __forceinline__ u64 fma2n(u64 a, u64 b, u64 c) {
    u64 d; asm("fma.rn.f32x2 %0, %1, %2, %3;" : "=l"(d) : "l"(a), "l"(b), "l"(c)); return d;
}
__device__ __forceinline__ u64 mul2(u64 a, u64 b) {
    u64 d; asm("mul.rn.f32x2 %0, %1, %2;" : "=l"(d) : "l"(a), "l"(b)); return d;
}
__device__ __forceinline__ u64 add2(u64 a, u64 b) {
    u64 d; asm("add.rn.f32x2 %0, %1, %2;" : "=l"(d) : "l"(a), "l"(b)); return d;
}
// packed leaky: leaky(v) = 0.505*v + 0.495*|v|
__device__ __forceinline__ u64 lk2(u64 v, u64 c505, u64 c495) {
    u64 a = v & 0x7fffffff7fffffffull;
    return fma2n(a, c495, mul2(v, c505));
}
__device__ __forceinline__ float leaky1(float v) {
    return fmaxf(v, 0.0f) + 0.01f * fminf(v, 0.0f);
}
// fire-and-forget L2 prefetch (no semantic effect; graph-safe)
__device__ __forceinline__ void pfL2(const void* p) {
    asm volatile("prefetch.global.L2 [%0];" :: "l"(p));
}

// ============================================================================
// Kernel 0: pack channel-pair weights into g_wp + zero g_accum.
// ============================================================================
__global__ __launch_bounds__(192) void k_pack(
    const float* __restrict__ w1, const float* __restrict__ b1,
    const float* __restrict__ w2, const float* __restrict__ b2)
{
    int i = blockIdx.x * 192 + threadIdx.x;
    if (i < 96) g_accum[i] = 0.0f;

    if (i < 384) {                       // w1 pairs: [jj][k], k in 0..31
        int jj = i >> 5, k = i & 31;
        g_wp[i] = pk2(w1[(2 * jj) * 32 + k], w1[(2 * jj + 1) * 32 + k]);
    } else if (i < 528) {                // w2 pairs: [jj][k], k in 0..23
        int t = i - 384, jj = t / 24, k = t % 24;
        g_wp[i] = pk2(w2[(2 * jj) * 24 + k], w2[(2 * jj + 1) * 24 + k]);
    } else if (i < 540) {                // b1 pairs
        int t = i - 528;
        g_wp[i] = pk2(b1[2 * t], b1[2 * t + 1]);
    } else if (i < WPN) {                // b2 pairs
        int t = i - 540;
        g_wp[i] = pk2(b2[2 * t], b2[2 * t + 1]);
    }
}

// ============================================================================
// Kernel 1: per-curve MLP 32->24->12 (leaky), per-group sum, global sum/sumsq.
// Champion structure (4 curves/lane, 128 thr, const weights); ONLY change:
// q-loop unroll 2 -> 4 to double in-flight x-load batches (MLP 16->32).
// ============================================================================
__global__ __launch_bounds__(128, 3) void k_curves(const float* __restrict__ x)
{
    __shared__ float sred[4][24];

    const int tid = threadIdx.x;
    const int lane = tid & 31, warp = tid >> 5;
    const int g = blockIdx.x * 4 + warp;

    const float4* r0 = (const float4*)x + ((size_t)g * CSEG + lane) * 8;
    // lane's 4 curves: rows lane, lane+32, lane+64, lane+96 -> +256 float4 apart

    // ---- layer 1: H[c][jj] = packed channels (2jj, 2jj+1) of curve c ----
    u64 H[4][12];
#pragma unroll
    for (int jj = 0; jj < 12; ++jj) {
        u64 b = c_wp[528 + jj];
#pragma unroll
        for (int c = 0; c < 4; ++c) H[c][jj] = b;
    }

#pragma unroll 4
    for (int q = 0; q < 8; ++q) {
        float4 xv0 = r0[q], xv1 = r0[q + 256], xv2 = r0[q + 512], xv3 = r0[q + 768];
        u64 d0x = dup2(xv0.x), d0y = dup2(xv0.y), d0z = dup2(xv0.z), d0w = dup2(xv0.w);
        u64 d1x = dup2(xv1.x), d1y = dup2(xv1.y), d1z = dup2(xv1.z), d1w = dup2(xv1.w);
        u64 d2x = dup2(xv2.x), d2y = dup2(xv2.y), d2z = dup2(xv2.z), d2w = dup2(xv2.w);
        u64 d3x = dup2(xv3.x), d3y = dup2(xv3.y), d3z = dup2(xv3.z), d3w = dup2(xv3.w);
#pragma unroll
        for (int jj = 0; jj < 12; ++jj) {
            u64 wa = c_wp[jj * 32 + 4 * q + 0];   // k = 4q
            u64 wb = c_wp[jj * 32 + 4 * q + 1];   // k = 4q+1
            u64 wc = c_wp[jj * 32 + 4 * q + 2];   // k = 4q+2
            u64 wd = c_wp[jj * 32 + 4 * q + 3];   // k = 4q+3
            fma2(H[0][jj], d0x, wa); fma2(H[1][jj], d1x, wa);
            fma2(H[2][jj], d2x, wa); fma2(H[3][jj], d3x, wa);
            fma2(H[0][jj], d0y, wb); fma2(H[1][jj], d1y, wb);
            fma2(H[2][jj], d2y, wb); fma2(H[3][jj], d3y, wb);
            fma2(H[0][jj], d0z, wc); fma2(H[1][jj], d1z, wc);
            fma2(H[2][jj], d2z, wc); fma2(H[3][jj], d3z, wc);
            fma2(H[0][jj], d0w, wd); fma2(H[1][jj], d1w, wd);
            fma2(H[2][jj], d2w, wd); fma2(H[3][jj], d3w, wd);
        }
    }

    const u64 C505 = dup2(0.505f), C495 = dup2(0.495f);
#pragma unroll
    for (int c = 0; c < 4; ++c)
#pragma unroll
        for (int jj = 0; jj < 12; ++jj) H[c][jj] = lk2(H[c][jj], C505, C495);

    // ---- layer 2: C[c][jj] = packed output channels (2jj, 2jj+1) ----
    u64 C[4][6];
#pragma unroll
    for (int jj = 0; jj < 6; ++jj) {
        u64 b = c_wp[540 + jj];
#pragma unroll
        for (int c = 0; c < 4; ++c) C[c][jj] = b;
    }

#pragma unroll
    for (int kk = 0; kk < 12; ++kk) {                 // input channels 2kk, 2kk+1
        u64 dlo[4], dhi[4];
#pragma unroll
        for (int c = 0; c < 4; ++c) {
            float lo, hi; unpk2(H[c][kk], lo, hi);
            dlo[c] = dup2(lo); dhi[c] = dup2(hi);
        }
#pragma unroll
        for (int jj = 0; jj < 6; ++jj) {
            u64 wlo = c_wp[384 + jj * 24 + 2 * kk];       // input 2kk
            u64 whi = c_wp[384 + jj * 24 + 2 * kk + 1];   // input 2kk+1
            fma2(C[0][jj], dlo[0], wlo); fma2(C[0][jj], dhi[0], whi);
            fma2(C[1][jj], dlo[1], wlo); fma2(C[1][jj], dhi[1], whi);
            fma2(C[2][jj], dlo[2], wlo); fma2(C[2][jj], dhi[2], whi);
            fma2(C[3][jj], dlo[3], wlo); fma2(C[3][jj], dhi[3], whi);
        }
    }

    // leaky + per-thread packed sum / sumsq over the 4 curves
    u64 S[6], Q[6];
#pragma unroll
    for (int jj = 0; jj < 6; ++jj) {
        u64 c0 = lk2(C[0][jj], C505, C495);
        u64 c1 = lk2(C[1][jj], C505, C495);
        u64 c2 = lk2(C[2][jj], C505, C495);
        u64 c3 = lk2(C[3][jj], C505, C495);
        S[jj] = add2(add2(c0, c1), add2(c2, c3));
        u64 q = mul2(c0, c0);
        q = fma2n(c1, c1, q);
        q = fma2n(c2, c2, q);
        Q[jj] = fma2n(c3, c3, q);
    }

    // warp reduction: warp == group (128 curves)
#pragma unroll
    for (int jj = 0; jj < 6; ++jj) {
#pragma unroll
        for (int off = 16; off > 0; off >>= 1) {
            S[jj] = add2(S[jj], (u64)__shfl_xor_sync(0xffffffffu, (unsigned long long)S[jj], off));
            Q[jj] = add2(Q[jj], (u64)__shfl_xor_sync(0xffffffffu, (unsigned long long)Q[jj], off));
        }
    }
    if (lane == 0) {
#pragma unroll
        for (int jj = 0; jj < 6; ++jj) {
            float slo, shi, qlo, qhi;
            unpk2(S[jj], slo, shi);
            unpk2(Q[jj], qlo, qhi);
            g_gsum[g * 12 + 2 * jj]     = slo;
            g_gsum[g * 12 + 2 * jj + 1] = shi;
            sred[warp][2 * jj]      = slo;
            sred[warp][2 * jj + 1]  = shi;
            sred[warp][12 + 2 * jj]     = qlo;
            sred[warp][12 + 2 * jj + 1] = qhi;
        }
    }
    __syncthreads();
    if (tid < 24)
        atomicAdd(&g_accum[tid],
                  sred[0][tid] + sred[1][tid] + sred[2][tid] + sred[3][tid]);
}

// ============================================================================
// Kernel 2: per-picture — deferred BN12 on group means, distance MLP,
// 3-level pooling -> g_sumpicT[36][256]; atomic global sum/sumsq for BN36.
// Block 0 L2-prefetches k_head's weights.
// ============================================================================
__global__ __launch_bounds__(64) void k_groups(
    const float* __restrict__ dist,
    const float* __restrict__ gamma12, const float* __restrict__ beta12,
    const float* __restrict__ wd, const float* __restrict__ bd,
    const float* __restrict__ gamma36, const float* __restrict__ beta36,
    const float* __restrict__ wp1, const float* __restrict__ bp1,
    const float* __restrict__ wp2, const float* __restrict__ bp2,
    const float* __restrict__ wp3, const float* __restrict__ bp3)
{
    __shared__ float sc[12], sh[12], wds[60], bds[12];
    __shared__ float red[2][36];
    const int tid = threadIdx.x, b = blockIdx.x;

    // ---- L2 warm-up for k_head (fire-and-forget) ----
    if (b == 0) {
        if (tid < 21) pfL2(wp1 + tid * 32);
        else if (tid < 26) pfL2(wp2 + (tid - 21) * 32);
        else if (tid == 26) { pfL2(wp3); pfL2(bp1); }
        else if (tid == 27) { pfL2(bp2); pfL2(bp3); }
        else if (tid == 28) { pfL2(gamma36); pfL2(beta36); }
        else if (tid == 29) { pfL2(gamma36 + 32); pfL2(beta36 + 32); }
    }

    if (tid < 12) {
        const float n = (float)NCURVE;
        float mu  = g_accum[tid] / n;
        float var = g_accum[12 + tid] / n - mu * mu;
        float ss  = gamma12[tid] * rsqrtf(var + EPSF);
        sc[tid] = ss;
        sh[tid] = beta12[tid] - mu * ss;
    }
    if (tid < 60) wds[tid] = wd[tid];
    if (tid < 12) bds[tid] = bd[tid];
    __syncthreads();

    const int bg = b * GPG + tid;
    const float4* gs4 = (const float4*)(g_gsum + bg * 12);
    float4 h0 = gs4[0], h1 = gs4[1], h2 = gs4[2];
    float h[12] = {h0.x, h0.y, h0.z, h0.w, h1.x, h1.y, h1.z, h1.w,
                   h2.x, h2.y, h2.z, h2.w};
#pragma unroll
    for (int j = 0; j < 12; ++j)
        h[j] = fmaf(h[j] * (1.0f / CSEG), sc[j], sh[j]);

    float d5[5];
#pragma unroll
    for (int k = 0; k < 5; ++k) d5[k] = dist[bg * 10 + k];

    float v[36];
#pragma unroll
    for (int j = 0; j < 12; ++j) {
        float t = bds[j];
#pragma unroll
        for (int k = 0; k < 5; ++k) t = fmaf(wds[j * 5 + k], d5[k], t);
        float cor = leaky1(t);
        float g2 = cor * h[j];
        float g3 = cor * g2;
        v[j] = h[j]; v[12 + j] = g2; v[24 + j] = g3;
    }
#pragma unroll
    for (int j = 0; j < 36; ++j) {
#pragma unroll
        for (int off = 16; off > 0; off >>= 1)
            v[j] += __shfl_xor_sync(0xffffffffu, v[j], off);
    }
    const int warp = tid >> 5;
    if ((tid & 31) == 0) {
#pragma unroll
        for (int j = 0; j < 36; ++j) red[warp][j] = v[j];
    }
    __syncthreads();
    if (tid < 36) {
        float val = (red[0][tid] + red[1][tid]) * (1.0f / GPG);
        g_sumpicT[tid * BPIC + b] = val;      // transposed store
        atomicAdd(&g_accum[24 + tid], val);
        atomicAdd(&g_accum[60 + tid], val * val);
    }
}

// ============================================================================
// Kernel 3: BN36 + head MLP 36->18->8 -> softmax. 8 blocks x 32 pictures.
// ============================================================================
__global__ __launch_bounds__(256) void k_head(
    const float* __restrict__ gamma36, const float* __restrict__ beta36,
    const float* __restrict__ wp1, const float* __restrict__ bp1,
    const float* __restrict__ wp2, const float* __restrict__ bp2,
    const float* __restrict__ wp3, const float* __restrict__ bp3,
    float* __restrict__ out)
{
    __shared__ float w1s[648], b1s[18], w2s[144], b2s[8], w3s[16], b3s[2];
    __shared__ float sc[36], sh[36];
    const int tid = threadIdx.x;

    for (int i = tid; i < 648; i += 256) w1s[i] = wp1[i];
    if (tid < 18)  b1s[tid] = bp1[tid];
    if (tid < 144) w2s[tid] = wp2[tid];
    if (tid < 8)   b2s[tid] = bp2[tid];
    if (tid < 16)  w3s[tid] = wp3[tid];
    if (tid < 2)   b3s[tid] = bp3[tid];

    if (tid < 36) {
        float mu  = g_accum[24 + tid] * (1.0f / 256.0f);
        float var = g_accum[60 + tid] * (1.0f / 256.0f) - mu * mu;
        float ss  = gamma36[tid] * rsqrtf(var + EPSF);
        sc[tid] = ss;
        sh[tid] = beta36[tid] - mu * ss;
    }
    __syncthreads();

    if (tid >= 32) return;                   // 32 pictures per block
    const int p = blockIdx.x * 32 + tid;

    float sN[36];
#pragma unroll
    for (int j = 0; j < 36; ++j)
        sN[j] = fmaf(g_sumpicT[j * BPIC + p], sc[j], sh[j]);

    float p1[18];
#pragma unroll
    for (int j = 0; j < 18; ++j) {
        float t = b1s[j];
#pragma unroll
        for (int k = 0; k < 36; ++k) t = fmaf(w1s[j * 36 + k], sN[k], t);
        p1[j] = leaky1(t);
    }
    float p2[8];
#pragma unroll
    for (int j = 0; j < 8; ++j) {
        float t = b2s[j];
#pragma unroll
        for (int k = 0; k < 18; ++k) t = fmaf(w2s[j * 18 + k], p1[k], t);
        p2[j] = leaky1(t);
    }
    float l0 = b3s[0], l1 = b3s[1];
#pragma unroll
    for (int k = 0; k < 8; ++k) {
        l0 = fmaf(w3s[k],     p2[k], l0);
        l1 = fmaf(w3s[8 + k], p2[k], l1);
    }
    float m  = fmaxf(l0, l1);
    float e0 = expf(l0 - m), e1 = expf(l1 - m);
    float inv = 1.0f / (e0 + e1);

#pragma unroll
    for (int j = 0; j < 8; ++j) out[p * 8 + j] = p2[j];   // p2: [256,8]
    out[BPIC * 8 + p * 2 + 0] = e0 * inv;                 // p3: [256,2]
    out[BPIC * 8 + p * 2 + 1] = e1 * inv;
}

// ============================================================================
extern "C" void kernel_launch(void* const* d_in, const int* in_sizes, int n_in,
                              void* d_out, int out_size)
{
    const float* x       = (const float*)d_in[0];
    const float* dist    = (const float*)d_in[1];
    // d_in[2] = segment_ids: structurally arange/128, unused
    const float* w1      = (const float*)d_in[3];
    const float* b1      = (const float*)d_in[4];
    const float* w2      = (const float*)d_in[5];
    const float* b2      = (const float*)d_in[6];
    const float* gamma12 = (const float*)d_in[7];
    const float* beta12  = (const float*)d_in[8];
    const float* wd      = (const float*)d_in[9];
    const float* bd      = (const float*)d_in[10];
    const float* gamma36 = (const float*)d_in[11];
    const float* beta36  = (const float*)d_in[12];
    const float* wp1     = (const float*)d_in[13];
    const float* bp1     = (const float*)d_in[14];
    const float* wp2     = (const float*)d_in[15];
    const float* bp2     = (const float*)d_in[16];
    const float* wp3     = (const float*)d_in[17];
    const float* bp3     = (const float*)d_in[18];

    // pack weights + zero g_accum, then stage into __constant__ via D2D copy
    k_pack<<<3, 192>>>(w1, b1, w2, b2);
    void* wpp = nullptr;
    cudaGetSymbolAddress(&wpp, g_wp);
    cudaMemcpyToSymbolAsync(c_wp, wpp, WPN * sizeof(u64), 0,
                            cudaMemcpyDeviceToDevice);

    k_curves<<<NGRP / 4, 128>>>(x);
    k_groups<<<BPIC, 64>>>(dist, gamma12, beta12, wd, bd,
                           gamma36, beta36, wp1, bp1, wp2, bp2, wp3, bp3);
    k_head<<<8, 256>>>(gamma36, beta36, wp1, bp1, wp2, bp2, wp3, bp3,
                       (float*)d_out);
}